// round 4
// baseline (speedup 1.0000x reference)
#include <cuda_runtime.h>
#include <cstdint>

#define NATOMS   100000
#define CUTOFF2  0.81f
#define PREFAC   138.93544539709032f

// Packed atom data: two float4 per atom, 32B aligned => one 32B L2 sector per atom.
// slot 2*i   : (x, y, z, charge)
// slot 2*i+1 : (sigma, epsilon, 0, 0)
__device__ float4 g_atoms[2 * NATOMS];

__global__ void pack_kernel(const float* __restrict__ coords,
                            const float* __restrict__ charges,
                            const float* __restrict__ sigma,
                            const float* __restrict__ epsilon,
                            float* __restrict__ out)
{
    int i = blockIdx.x * blockDim.x + threadIdx.x;
    if (i == 0) out[0] = 0.0f;   // zero the poisoned output (ordered before energy kernel)
    if (i < NATOMS) {
        float4 a;
        a.x = coords[3 * i + 0];
        a.y = coords[3 * i + 1];
        a.z = coords[3 * i + 2];
        a.w = charges[i];
        g_atoms[2 * i] = a;
        float4 b;
        b.x = sigma[i];
        b.y = epsilon[i];
        b.z = 0.0f;
        b.w = 0.0f;
        g_atoms[2 * i + 1] = b;
    }
}

// Tail math: only for pairs inside the cutoff (~0.3%).
// Second atom-record halves are same-sector L1 hits.
__device__ __forceinline__ float pair_energy(int i, int j, float r2,
                                             float qi, float qj)
{
    const float4 bi = __ldg(&g_atoms[2 * i + 1]);
    const float4 bj = __ldg(&g_atoms[2 * j + 1]);

    const float inv_r  = rsqrtf(r2);
    const float inv_r2 = 1.0f / r2;

    const float e_coul = PREFAC * qi * qj * inv_r;

    const float sig = 0.5f * (bi.x + bj.x);
    const float eps = sqrtf(bi.y * bj.y);
    const float sr2 = sig * sig * inv_r2;
    const float sr6 = sr2 * sr2 * sr2;
    return fmaf(4.0f * eps, sr6 * sr6 - sr6, e_coul);
}

__global__ __launch_bounds__(256, 7) void energy_kernel(const int4* __restrict__ pairs2,
                                                        const float* __restrict__ box,
                                                        float* __restrict__ out,
                                                        int npairs2)
{
    const float bx = __ldg(box + 0);
    const float by = __ldg(box + 4);
    const float bz = __ldg(box + 8);
    const float ibx = 1.0f / bx;
    const float iby = 1.0f / by;
    const float ibz = 1.0f / bz;

    float acc = 0.0f;

    const int stride = gridDim.x * blockDim.x;
    int idx = blockIdx.x * blockDim.x + threadIdx.x;

    // Software pipeline: pair record for iteration k is loaded during iteration k-1.
    int4 p;
    bool have = idx < npairs2;
    if (have) p = __ldcs(pairs2 + idx);

    while (have) {
        // 1) Gathers for the current (already-resident) pair record: issue first, MLP=4.
        const float4 ai0 = __ldg(&g_atoms[2 * p.x]);
        const float4 aj0 = __ldg(&g_atoms[2 * p.y]);
        const float4 ai1 = __ldg(&g_atoms[2 * p.z]);
        const float4 aj1 = __ldg(&g_atoms[2 * p.w]);

        // 2) Prefetch next pair record; its latency overlaps the gathers + compute below.
        const int nidx = idx + stride;
        const bool have_n = nidx < npairs2;
        int4 pn;
        if (have_n) pn = __ldcs(pairs2 + nidx);

        // 3) Compute current two pairs.
        {
            float dx = ai0.x - aj0.x;
            float dy = ai0.y - aj0.y;
            float dz = ai0.z - aj0.z;
            dx -= bx * rintf(dx * ibx);
            dy -= by * rintf(dy * iby);
            dz -= bz * rintf(dz * ibz);
            const float r2 = fmaf(dx, dx, fmaf(dy, dy, dz * dz));
            if (r2 < CUTOFF2) {
                if (((p.x / 3) != (p.y / 3)) && (p.x != p.y))
                    acc += pair_energy(p.x, p.y, r2, ai0.w, aj0.w);
            }
        }
        {
            float dx = ai1.x - aj1.x;
            float dy = ai1.y - aj1.y;
            float dz = ai1.z - aj1.z;
            dx -= bx * rintf(dx * ibx);
            dy -= by * rintf(dy * iby);
            dz -= bz * rintf(dz * ibz);
            const float r2 = fmaf(dx, dx, fmaf(dy, dy, dz * dz));
            if (r2 < CUTOFF2) {
                if (((p.z / 3) != (p.w / 3)) && (p.z != p.w))
                    acc += pair_energy(p.z, p.w, r2, ai1.w, aj1.w);
            }
        }

        p = pn;
        idx = nidx;
        have = have_n;
    }

    // warp reduction
    #pragma unroll
    for (int off = 16; off > 0; off >>= 1)
        acc += __shfl_down_sync(0xFFFFFFFFu, acc, off);

    __shared__ float warp_sums[8];
    const int lane = threadIdx.x & 31;
    const int wid  = threadIdx.x >> 5;
    if (lane == 0) warp_sums[wid] = acc;
    __syncthreads();

    if (wid == 0) {
        float v = (lane < (blockDim.x >> 5)) ? warp_sums[lane] : 0.0f;
        #pragma unroll
        for (int off = 4; off > 0; off >>= 1)
            v += __shfl_down_sync(0xFFFFFFFFu, v, off);
        if (lane == 0)
            atomicAdd(out, v);
    }
}

extern "C" void kernel_launch(void* const* d_in, const int* in_sizes, int n_in,
                              void* d_out, int out_size)
{
    const float* coords  = (const float*)d_in[0];  // [N,3]
    const float* box     = (const float*)d_in[1];  // [3,3]
    const float* charges = (const float*)d_in[2];  // [N]
    const float* sigma   = (const float*)d_in[3];  // [N]
    const float* epsilon = (const float*)d_in[4];  // [N]
    const int4*  pairs2  = (const int4*)d_in[5];   // [NPAIRS,2] as [NPAIRS/2, 4]
    float* out = (float*)d_out;

    const int npairs2 = in_sizes[5] / 4;

    {
        const int threads = 256;
        const int blocks = (NATOMS + threads - 1) / threads;
        pack_kernel<<<blocks, threads>>>(coords, charges, sigma, epsilon, out);
    }
    {
        const int threads = 256;
        const int blocks = 4096;
        energy_kernel<<<blocks, threads>>>(pairs2, box, out, npairs2);
    }
}

// round 6
// speedup vs baseline: 1.0697x; 1.0697x over previous
#include <cuda_runtime.h>
#include <cstdint>

#define NATOMS   100000
#define CUTOFF2  0.81f
#define PREFAC   138.93544539709032f

// Packed atom data: two float4 per atom, 32B aligned => one 32B L2 sector per atom.
// slot 2*i   : (x, y, z, charge)
// slot 2*i+1 : (sigma, epsilon, 0, 0)
__device__ float4 g_atoms[2 * NATOMS];

__global__ void pack_kernel(const float* __restrict__ coords,
                            const float* __restrict__ charges,
                            const float* __restrict__ sigma,
                            const float* __restrict__ epsilon,
                            float* __restrict__ out)
{
    int i = blockIdx.x * blockDim.x + threadIdx.x;
    if (i == 0) out[0] = 0.0f;   // zero the poisoned output (ordered before energy kernel)
    if (i < NATOMS) {
        float4 a;
        a.x = coords[3 * i + 0];
        a.y = coords[3 * i + 1];
        a.z = coords[3 * i + 2];
        a.w = charges[i];
        g_atoms[2 * i] = a;
        float4 b;
        b.x = sigma[i];
        b.y = epsilon[i];
        b.z = 0.0f;
        b.w = 0.0f;
        g_atoms[2 * i + 1] = b;
    }
}

// Tail math: only for pairs inside the cutoff (~0.3%).
// Second atom-record halves are same-sector L1 hits.
__device__ __forceinline__ float pair_energy(int i, int j, float r2,
                                             float qi, float qj)
{
    const float4 bi = __ldg(&g_atoms[2 * i + 1]);
    const float4 bj = __ldg(&g_atoms[2 * j + 1]);

    const float inv_r  = rsqrtf(r2);
    const float inv_r2 = 1.0f / r2;

    const float e_coul = PREFAC * qi * qj * inv_r;

    const float sig = 0.5f * (bi.x + bj.x);
    const float eps = sqrtf(bi.y * bj.y);
    const float sr2 = sig * sig * inv_r2;
    const float sr6 = sr2 * sr2 * sr2;
    return fmaf(4.0f * eps, sr6 * sr6 - sr6, e_coul);
}

__global__ __launch_bounds__(256, 8) void energy_kernel(const int4* __restrict__ pairs2,
                                                        const float* __restrict__ box,
                                                        float* __restrict__ out,
                                                        int npairs2)
{
    const float bx = __ldg(box + 0);
    const float by = __ldg(box + 4);
    const float bz = __ldg(box + 8);
    const float ibx = 1.0f / bx;
    const float iby = 1.0f / by;
    const float ibz = 1.0f / bz;

    float acc = 0.0f;

    const int stride = gridDim.x * blockDim.x;
    for (int idx = blockIdx.x * blockDim.x + threadIdx.x; idx < npairs2; idx += stride) {
        const int4 p = __ldcs(pairs2 + idx);   // streaming: evict-first, keep L1 for atoms

        // Four divergent gathers back-to-back (MLP=4) before any compute.
        const float4 ai0 = __ldg(&g_atoms[2 * p.x]);
        const float4 aj0 = __ldg(&g_atoms[2 * p.y]);
        const float4 ai1 = __ldg(&g_atoms[2 * p.z]);
        const float4 aj1 = __ldg(&g_atoms[2 * p.w]);

        // ---- pair 0 ----
        {
            float dx = ai0.x - aj0.x;
            float dy = ai0.y - aj0.y;
            float dz = ai0.z - aj0.z;
            dx -= bx * rintf(dx * ibx);
            dy -= by * rintf(dy * iby);
            dz -= bz * rintf(dz * ibz);
            const float r2 = fmaf(dx, dx, fmaf(dy, dy, dz * dz));
            if (r2 < CUTOFF2) {                       // cheap test first: skips divides for 99.7%
                if (((p.x / 3) != (p.y / 3)) && (p.x != p.y))
                    acc += pair_energy(p.x, p.y, r2, ai0.w, aj0.w);
            }
        }
        // ---- pair 1 ----
        {
            float dx = ai1.x - aj1.x;
            float dy = ai1.y - aj1.y;
            float dz = ai1.z - aj1.z;
            dx -= bx * rintf(dx * ibx);
            dy -= by * rintf(dy * iby);
            dz -= bz * rintf(dz * ibz);
            const float r2 = fmaf(dx, dx, fmaf(dy, dy, dz * dz));
            if (r2 < CUTOFF2) {
                if (((p.z / 3) != (p.w / 3)) && (p.z != p.w))
                    acc += pair_energy(p.z, p.w, r2, ai1.w, aj1.w);
            }
        }
    }

    // warp reduction
    #pragma unroll
    for (int off = 16; off > 0; off >>= 1)
        acc += __shfl_down_sync(0xFFFFFFFFu, acc, off);

    __shared__ float warp_sums[8];
    const int lane = threadIdx.x & 31;
    const int wid  = threadIdx.x >> 5;
    if (lane == 0) warp_sums[wid] = acc;
    __syncthreads();

    if (wid == 0) {
        float v = (lane < (blockDim.x >> 5)) ? warp_sums[lane] : 0.0f;
        #pragma unroll
        for (int off = 4; off > 0; off >>= 1)
            v += __shfl_down_sync(0xFFFFFFFFu, v, off);
        if (lane == 0)
            atomicAdd(out, v);
    }
}

extern "C" void kernel_launch(void* const* d_in, const int* in_sizes, int n_in,
                              void* d_out, int out_size)
{
    const float* coords  = (const float*)d_in[0];  // [N,3]
    const float* box     = (const float*)d_in[1];  // [3,3]
    const float* charges = (const float*)d_in[2];  // [N]
    const float* sigma   = (const float*)d_in[3];  // [N]
    const float* epsilon = (const float*)d_in[4];  // [N]
    const int4*  pairs2  = (const int4*)d_in[5];   // [NPAIRS,2] as [NPAIRS/2, 4]
    float* out = (float*)d_out;

    const int npairs2 = in_sizes[5] / 4;

    {
        const int threads = 256;
        const int blocks = (NATOMS + threads - 1) / threads;
        pack_kernel<<<blocks, threads>>>(coords, charges, sigma, epsilon, out);
    }
    {
        // Persistent single wave: 148 SMs x 8 resident blocks (32 regs, 256 thr).
        // 4096 blocks was 3.46 waves -> ~16% straggler-wave idle; 1184 is exactly 1.
        const int threads = 256;
        const int blocks = 1184;
        energy_kernel<<<blocks, threads>>>(pairs2, box, out, npairs2);
    }
}

// round 7
// speedup vs baseline: 1.0894x; 1.0184x over previous
#include <cuda_runtime.h>
#include <cstdint>

#define NATOMS   100000
#define CUTOFF2  0.81f
#define PREFAC   138.93544539709032f

// Packed atom data: two float4 per atom, 32B aligned => one 32B L2 sector per atom.
// slot 2*i   : (x, y, z, charge)
// slot 2*i+1 : (sigma, epsilon, 0, 0)
__device__ float4 g_atoms[2 * NATOMS];

// Work-stealing chunk counter (reset by pack_kernel each launch; same-stream ordering).
__device__ int g_next_chunk;

#define CHUNK_I4 128        // int4 records per stolen chunk (= 4 coalesced warp-iterations)

__global__ void pack_kernel(const float* __restrict__ coords,
                            const float* __restrict__ charges,
                            const float* __restrict__ sigma,
                            const float* __restrict__ epsilon,
                            float* __restrict__ out)
{
    int i = blockIdx.x * blockDim.x + threadIdx.x;
    if (i == 0) {
        out[0] = 0.0f;       // zero the poisoned output
        g_next_chunk = 0;    // reset work-stealing counter for this launch
    }
    if (i < NATOMS) {
        float4 a;
        a.x = coords[3 * i + 0];
        a.y = coords[3 * i + 1];
        a.z = coords[3 * i + 2];
        a.w = charges[i];
        g_atoms[2 * i] = a;
        float4 b;
        b.x = sigma[i];
        b.y = epsilon[i];
        b.z = 0.0f;
        b.w = 0.0f;
        g_atoms[2 * i + 1] = b;
    }
}

// Tail math: only for pairs inside the cutoff (~0.3%).
__device__ __forceinline__ float pair_energy(int i, int j, float r2,
                                             float qi, float qj)
{
    const float4 bi = __ldg(&g_atoms[2 * i + 1]);   // same 32B sector as coords -> L1 hit
    const float4 bj = __ldg(&g_atoms[2 * j + 1]);

    const float inv_r  = rsqrtf(r2);
    const float inv_r2 = 1.0f / r2;

    const float e_coul = PREFAC * qi * qj * inv_r;

    const float sig = 0.5f * (bi.x + bj.x);
    const float eps = sqrtf(bi.y * bj.y);
    const float sr2 = sig * sig * inv_r2;
    const float sr6 = sr2 * sr2 * sr2;
    return fmaf(4.0f * eps, sr6 * sr6 - sr6, e_coul);
}

__global__ __launch_bounds__(256, 7) void energy_kernel(const int4* __restrict__ pairs2,
                                                        const float* __restrict__ box,
                                                        float* __restrict__ out,
                                                        int npairs2)
{
    const float bx = __ldg(box + 0);
    const float by = __ldg(box + 4);
    const float bz = __ldg(box + 8);
    const float ibx = 1.0f / bx;
    const float iby = 1.0f / by;
    const float ibz = 1.0f / bz;

    const int lane = threadIdx.x & 31;
    const int nchunks = (npairs2 + CHUNK_I4 - 1) / CHUNK_I4;

    float acc = 0.0f;

    // Warp-level work stealing: lane 0 grabs a chunk, broadcast, 4 coalesced iterations.
    for (;;) {
        int chunk;
        if (lane == 0) chunk = atomicAdd(&g_next_chunk, 1);
        chunk = __shfl_sync(0xFFFFFFFFu, chunk, 0);
        if (chunk >= nchunks) break;

        const int base = chunk * CHUNK_I4 + lane;

        for (int k = 0; k < CHUNK_I4 / 32; k++) {
            const int idx = base + k * 32;
            if (idx >= npairs2) break;

            const int4 p = __ldcs(pairs2 + idx);   // streaming: keep L1 for atom gathers

            // Four divergent gathers back-to-back (MLP=4) before any compute.
            const float4 ai0 = __ldg(&g_atoms[2 * p.x]);
            const float4 aj0 = __ldg(&g_atoms[2 * p.y]);
            const float4 ai1 = __ldg(&g_atoms[2 * p.z]);
            const float4 aj1 = __ldg(&g_atoms[2 * p.w]);

            // ---- pair 0 ----
            {
                float dx = ai0.x - aj0.x;
                float dy = ai0.y - aj0.y;
                float dz = ai0.z - aj0.z;
                dx -= bx * rintf(dx * ibx);
                dy -= by * rintf(dy * iby);
                dz -= bz * rintf(dz * ibz);
                const float r2 = fmaf(dx, dx, fmaf(dy, dy, dz * dz));
                if (r2 < CUTOFF2) {
                    if (((p.x / 3) != (p.y / 3)) && (p.x != p.y))
                        acc += pair_energy(p.x, p.y, r2, ai0.w, aj0.w);
                }
            }
            // ---- pair 1 ----
            {
                float dx = ai1.x - aj1.x;
                float dy = ai1.y - aj1.y;
                float dz = ai1.z - aj1.z;
                dx -= bx * rintf(dx * ibx);
                dy -= by * rintf(dy * iby);
                dz -= bz * rintf(dz * ibz);
                const float r2 = fmaf(dx, dx, fmaf(dy, dy, dz * dz));
                if (r2 < CUTOFF2) {
                    if (((p.z / 3) != (p.w / 3)) && (p.z != p.w))
                        acc += pair_energy(p.z, p.w, r2, ai1.w, aj1.w);
                }
            }
        }
    }

    // warp reduction
    #pragma unroll
    for (int off = 16; off > 0; off >>= 1)
        acc += __shfl_down_sync(0xFFFFFFFFu, acc, off);

    __shared__ float warp_sums[8];
    const int wid = threadIdx.x >> 5;
    if (lane == 0) warp_sums[wid] = acc;
    __syncthreads();

    if (wid == 0) {
        float v = (lane < (blockDim.x >> 5)) ? warp_sums[lane] : 0.0f;
        #pragma unroll
        for (int off = 4; off > 0; off >>= 1)
            v += __shfl_down_sync(0xFFFFFFFFu, v, off);
        if (lane == 0)
            atomicAdd(out, v);
    }
}

extern "C" void kernel_launch(void* const* d_in, const int* in_sizes, int n_in,
                              void* d_out, int out_size)
{
    const float* coords  = (const float*)d_in[0];  // [N,3]
    const float* box     = (const float*)d_in[1];  // [3,3]
    const float* charges = (const float*)d_in[2];  // [N]
    const float* sigma   = (const float*)d_in[3];  // [N]
    const float* epsilon = (const float*)d_in[4];  // [N]
    const int4*  pairs2  = (const int4*)d_in[5];   // [NPAIRS,2] as [NPAIRS/2, 4]
    float* out = (float*)d_out;

    const int npairs2 = in_sizes[5] / 4;

    {
        const int threads = 256;
        const int blocks = (NATOMS + threads - 1) / threads;
        pack_kernel<<<blocks, threads>>>(coords, charges, sigma, epsilon, out);
    }
    {
        // Oversubscribed persistent grid: resident blocks (7-8/SM) steal chunks until
        // the counter is exhausted; surplus blocks find no work and exit immediately.
        const int threads = 256;
        const int blocks = 2368;   // 2 x 148 x 8
        energy_kernel<<<blocks, threads>>>(pairs2, box, out, npairs2);
    }
}

// round 8
// speedup vs baseline: 1.2389x; 1.1372x over previous
#include <cuda_runtime.h>
#include <cstdint>

#define NATOMS   100000
#define CUTOFF2  0.81f
#define PREFAC   138.93544539709032f

// Packed atom data: two float4 per atom, 32B aligned => one 32B L2 sector per atom.
// slot 2*i   : (x, y, z, charge)
// slot 2*i+1 : (sigma, epsilon, 0, 0)
__device__ float4 g_atoms[2 * NATOMS];

__global__ void pack_kernel(const float* __restrict__ coords,
                            const float* __restrict__ charges,
                            const float* __restrict__ sigma,
                            const float* __restrict__ epsilon,
                            float* __restrict__ out)
{
    int i = blockIdx.x * blockDim.x + threadIdx.x;
    if (i == 0) out[0] = 0.0f;   // zero the poisoned output (ordered before energy kernel)
    if (i < NATOMS) {
        float4 a;
        a.x = coords[3 * i + 0];
        a.y = coords[3 * i + 1];
        a.z = coords[3 * i + 2];
        a.w = charges[i];
        g_atoms[2 * i] = a;
        float4 b;
        b.x = sigma[i];
        b.y = epsilon[i];
        b.z = 0.0f;
        b.w = 0.0f;
        g_atoms[2 * i + 1] = b;
    }
}

// Tail math: only for pairs inside the cutoff (~0.3%).
// Second atom-record halves are same-sector L1 hits.
__device__ __forceinline__ float pair_energy(int i, int j, float r2,
                                             float qi, float qj)
{
    const float4 bi = __ldg(&g_atoms[2 * i + 1]);
    const float4 bj = __ldg(&g_atoms[2 * j + 1]);

    const float inv_r  = rsqrtf(r2);
    const float inv_r2 = 1.0f / r2;

    const float e_coul = PREFAC * qi * qj * inv_r;

    const float sig = 0.5f * (bi.x + bj.x);
    const float eps = sqrtf(bi.y * bj.y);
    const float sr2 = sig * sig * inv_r2;
    const float sr6 = sr2 * sr2 * sr2;
    return fmaf(4.0f * eps, sr6 * sr6 - sr6, e_coul);
}

__global__ __launch_bounds__(256, 8) void energy_kernel(const int4* __restrict__ pairs2,
                                                        const float* __restrict__ box,
                                                        float* __restrict__ out,
                                                        int npairs2)
{
    const float bx = __ldg(box + 0);
    const float by = __ldg(box + 4);
    const float bz = __ldg(box + 8);
    const float ibx = 1.0f / bx;
    const float iby = 1.0f / by;
    const float ibz = 1.0f / bz;

    float acc = 0.0f;

    const int stride = gridDim.x * blockDim.x;
    for (int idx = blockIdx.x * blockDim.x + threadIdx.x; idx < npairs2; idx += stride) {
        // Prefetch NEXT iteration's pair record into L2. Address is dependence-free,
        // so the DRAM->L2 latency (~577cyc) overlaps this whole iteration; the next
        // iteration's critical pair load then costs only an L2 hit (~234cyc).
        {
            int nidx = idx + stride;
            if (nidx >= npairs2) nidx = idx;          // clamp: keep address valid
            asm volatile("prefetch.global.L2 [%0];" :: "l"(pairs2 + nidx));
        }

        const int4 p = __ldcs(pairs2 + idx);   // streaming: evict-first, keep L1 for atoms

        // Four divergent gathers back-to-back (MLP=4) before any compute.
        const float4 ai0 = __ldg(&g_atoms[2 * p.x]);
        const float4 aj0 = __ldg(&g_atoms[2 * p.y]);
        const float4 ai1 = __ldg(&g_atoms[2 * p.z]);
        const float4 aj1 = __ldg(&g_atoms[2 * p.w]);

        // ---- pair 0 ----
        {
            float dx = ai0.x - aj0.x;
            float dy = ai0.y - aj0.y;
            float dz = ai0.z - aj0.z;
            dx -= bx * rintf(dx * ibx);
            dy -= by * rintf(dy * iby);
            dz -= bz * rintf(dz * ibz);
            const float r2 = fmaf(dx, dx, fmaf(dy, dy, dz * dz));
            if (r2 < CUTOFF2) {                       // cheap test first: skips divides for 99.7%
                if (((p.x / 3) != (p.y / 3)) && (p.x != p.y))
                    acc += pair_energy(p.x, p.y, r2, ai0.w, aj0.w);
            }
        }
        // ---- pair 1 ----
        {
            float dx = ai1.x - aj1.x;
            float dy = ai1.y - aj1.y;
            float dz = ai1.z - aj1.z;
            dx -= bx * rintf(dx * ibx);
            dy -= by * rintf(dy * iby);
            dz -= bz * rintf(dz * ibz);
            const float r2 = fmaf(dx, dx, fmaf(dy, dy, dz * dz));
            if (r2 < CUTOFF2) {
                if (((p.z / 3) != (p.w / 3)) && (p.z != p.w))
                    acc += pair_energy(p.z, p.w, r2, ai1.w, aj1.w);
            }
        }
    }

    // warp reduction
    #pragma unroll
    for (int off = 16; off > 0; off >>= 1)
        acc += __shfl_down_sync(0xFFFFFFFFu, acc, off);

    __shared__ float warp_sums[8];
    const int lane = threadIdx.x & 31;
    const int wid  = threadIdx.x >> 5;
    if (lane == 0) warp_sums[wid] = acc;
    __syncthreads();

    if (wid == 0) {
        float v = (lane < (blockDim.x >> 5)) ? warp_sums[lane] : 0.0f;
        #pragma unroll
        for (int off = 4; off > 0; off >>= 1)
            v += __shfl_down_sync(0xFFFFFFFFu, v, off);
        if (lane == 0)
            atomicAdd(out, v);
    }
}

extern "C" void kernel_launch(void* const* d_in, const int* in_sizes, int n_in,
                              void* d_out, int out_size)
{
    const float* coords  = (const float*)d_in[0];  // [N,3]
    const float* box     = (const float*)d_in[1];  // [3,3]
    const float* charges = (const float*)d_in[2];  // [N]
    const float* sigma   = (const float*)d_in[3];  // [N]
    const float* epsilon = (const float*)d_in[4];  // [N]
    const int4*  pairs2  = (const int4*)d_in[5];   // [NPAIRS,2] as [NPAIRS/2, 4]
    float* out = (float*)d_out;

    const int npairs2 = in_sizes[5] / 4;

    {
        const int threads = 256;
        const int blocks = (NATOMS + threads - 1) / threads;
        pack_kernel<<<blocks, threads>>>(coords, charges, sigma, epsilon, out);
    }
    {
        // 4736 = 4 x 148 x 8: exact multiple of the resident-block count, so the
        // final generation is full (no fractional-wave straggler tail).
        const int threads = 256;
        const int blocks = 4736;
        energy_kernel<<<blocks, threads>>>(pairs2, box, out, npairs2);
    }
}